// round 1
// baseline (speedup 1.0000x reference)
#include <cuda_runtime.h>
#include <cuda_bf16.h>
#include <math.h>

// ---------------------------------------------------------------------------
// Problem constants
// ---------------------------------------------------------------------------
#define BB     2
#define SS     1024
#define TT     (BB*SS)        // 2048 tokens
#define HID    2048
#define NH     32
#define HD     64
#define ROT    16
#define DFF    8192
#define LN_EPS 1e-5f

// ---------------------------------------------------------------------------
// Static scratch (no allocations allowed)
// ---------------------------------------------------------------------------
__device__ float g_xln[(size_t)TT * HID];
__device__ float g_q  [(size_t)TT * HID];
__device__ float g_k  [(size_t)TT * HID];
__device__ float g_v  [(size_t)TT * HID];
__device__ float g_sc [(size_t)BB * NH * SS * SS];   // 256 MB scores
__device__ float g_ctx[(size_t)TT * HID];
__device__ float g_h  [(size_t)TT * HID];
__device__ float g_yln[(size_t)TT * HID];
__device__ float g_gate[(size_t)TT * DFF];
__device__ float g_up [(size_t)TT * DFF];

// ---------------------------------------------------------------------------
// LayerNorm: one block (256 thr) per token, 2048 features
// ---------------------------------------------------------------------------
__global__ void __launch_bounds__(256) layernorm_kernel(
    const float* __restrict__ x, const float* __restrict__ w,
    const float* __restrict__ b, float* __restrict__ out)
{
    const int t   = blockIdx.x;
    const int tid = threadIdx.x;
    const float* xr = x + (size_t)t * HID;

    float v[8];
    float s = 0.f, s2 = 0.f;
#pragma unroll
    for (int i = 0; i < 8; i++) {
        v[i] = xr[tid + i * 256];
        s  += v[i];
        s2 += v[i] * v[i];
    }
#pragma unroll
    for (int o = 16; o; o >>= 1) {
        s  += __shfl_xor_sync(0xffffffffu, s,  o);
        s2 += __shfl_xor_sync(0xffffffffu, s2, o);
    }
    __shared__ float ss[8], ss2[8];
    if ((tid & 31) == 0) { ss[tid >> 5] = s; ss2[tid >> 5] = s2; }
    __syncthreads();
    if (tid < 32) {
        s  = (tid < 8) ? ss [tid] : 0.f;
        s2 = (tid < 8) ? ss2[tid] : 0.f;
#pragma unroll
        for (int o = 4; o; o >>= 1) {
            s  += __shfl_xor_sync(0xffffffffu, s,  o);
            s2 += __shfl_xor_sync(0xffffffffu, s2, o);
        }
        if (tid == 0) { ss[0] = s; ss2[0] = s2; }
    }
    __syncthreads();
    const float mean = ss[0] * (1.f / HID);
    const float var  = ss2[0] * (1.f / HID) - mean * mean;
    const float rstd = rsqrtf(var + LN_EPS);
    float* orow = out + (size_t)t * HID;
#pragma unroll
    for (int i = 0; i < 8; i++) {
        const int idx = tid + i * 256;
        orow[idx] = (v[i] - mean) * rstd * w[idx] + b[idx];
    }
}

// ---------------------------------------------------------------------------
// SGEMM NT:  C[M,N] = A[M,K] * B[N,K]^T  (+ optional elementwise addend)
// 128x128 tile, BK=16, 256 threads, 8x8 microtile. M,N % 128 == 0, K % 16 == 0
// ---------------------------------------------------------------------------
__global__ void __launch_bounds__(256) sgemm_nt_kernel(
    const float* __restrict__ A, const float* __restrict__ B,
    const float* __restrict__ add, float* __restrict__ C,
    int M, int N, int K)
{
    __shared__ float As[16][128];
    __shared__ float Bs[16][128];

    const int bx = blockIdx.x, by = blockIdx.y;
    const int tid = threadIdx.x;
    const int tx = tid & 15, ty = tid >> 4;

    const float* Ab = A + (size_t)by * 128 * K;
    const float* Bb = B + (size_t)bx * 128 * K;

    const int lr = tid >> 1;          // 0..127
    const int lc = (tid & 1) * 8;     // 0 or 8

    float acc[8][8];
#pragma unroll
    for (int i = 0; i < 8; i++)
#pragma unroll
        for (int j = 0; j < 8; j++) acc[i][j] = 0.f;

    for (int k0 = 0; k0 < K; k0 += 16) {
        const float4 a0 = *(const float4*)(Ab + (size_t)lr * K + k0 + lc);
        const float4 a1 = *(const float4*)(Ab + (size_t)lr * K + k0 + lc + 4);
        const float4 b0 = *(const float4*)(Bb + (size_t)lr * K + k0 + lc);
        const float4 b1 = *(const float4*)(Bb + (size_t)lr * K + k0 + lc + 4);
        As[lc+0][lr] = a0.x; As[lc+1][lr] = a0.y; As[lc+2][lr] = a0.z; As[lc+3][lr] = a0.w;
        As[lc+4][lr] = a1.x; As[lc+5][lr] = a1.y; As[lc+6][lr] = a1.z; As[lc+7][lr] = a1.w;
        Bs[lc+0][lr] = b0.x; Bs[lc+1][lr] = b0.y; Bs[lc+2][lr] = b0.z; Bs[lc+3][lr] = b0.w;
        Bs[lc+4][lr] = b1.x; Bs[lc+5][lr] = b1.y; Bs[lc+6][lr] = b1.z; Bs[lc+7][lr] = b1.w;
        __syncthreads();
#pragma unroll
        for (int kk = 0; kk < 16; kk++) {
            float ar[8], br[8];
            *(float4*)(ar)     = *(const float4*)&As[kk][ty * 8];
            *(float4*)(ar + 4) = *(const float4*)&As[kk][ty * 8 + 4];
            *(float4*)(br)     = *(const float4*)&Bs[kk][tx * 8];
            *(float4*)(br + 4) = *(const float4*)&Bs[kk][tx * 8 + 4];
#pragma unroll
            for (int i = 0; i < 8; i++)
#pragma unroll
                for (int j = 0; j < 8; j++)
                    acc[i][j] += ar[i] * br[j];
        }
        __syncthreads();
    }

#pragma unroll
    for (int i = 0; i < 8; i++) {
        const size_t row = (size_t)by * 128 + ty * 8 + i;
        float* Cr = C + row * N + bx * 128 + tx * 8;
        if (add) {
            const float* Ar = add + row * N + bx * 128 + tx * 8;
#pragma unroll
            for (int j = 0; j < 8; j++) Cr[j] = acc[i][j] + Ar[j];
        } else {
#pragma unroll
            for (int j = 0; j < 8; j++) Cr[j] = acc[i][j];
        }
    }
}

// ---------------------------------------------------------------------------
// Partial RoPE on first 16 dims of each head (q and k), pairs (i, i+8)
// ---------------------------------------------------------------------------
__global__ void __launch_bounds__(256) rope_kernel(
    float* __restrict__ q, float* __restrict__ k, const int* __restrict__ pos_ids)
{
    const int idx = blockIdx.x * blockDim.x + threadIdx.x;   // TT*NH*8 total
    if (idx >= TT * NH * 8) return;
    const int i = idx & 7;
    const int h = (idx >> 3) & 31;
    const int t = idx >> 8;
    const int b = t / SS, s = t % SS;
    const int pos = pos_ids[b * SS + s];

    const float freq = powf(10000.0f, -(2.0f * (float)i) / (float)ROT);
    const float ang  = (float)pos * freq;
    float c, si;
    sincosf(ang, &si, &c);

    const size_t base = (size_t)t * HID + h * HD;
    float q0 = q[base + i], q1 = q[base + i + 8];
    q[base + i]     = q0 * c - q1 * si;
    q[base + i + 8] = q1 * c + q0 * si;
    float k0 = k[base + i], k1 = k[base + i + 8];
    k[base + i]     = k0 * c - k1 * si;
    k[base + i + 8] = k1 * c + k0 * si;
}

// ---------------------------------------------------------------------------
// Attention scores: S[bh, q, k] = (Q . K)/8 + mask ; 64x64 tile per block
// grid: (S/64 ktiles, S/64 qtiles, B*NH), 256 threads, 4x4 per thread
// ---------------------------------------------------------------------------
__global__ void __launch_bounds__(256) attn_scores_kernel(
    const float* __restrict__ q, const float* __restrict__ k,
    const float* __restrict__ mask, float* __restrict__ scores)
{
    const int bh = blockIdx.z;
    const int b = bh >> 5, h = bh & 31;
    const int q0 = blockIdx.y * 64, k0 = blockIdx.x * 64;

    __shared__ float Qs[64][68];   // [d][q]
    __shared__ float Ks[64][68];   // [d][k]

    const int tid  = threadIdx.x;
    const int lrow = tid & 63;
    const int dch  = (tid >> 6) * 16;

    const float* qg = q + ((size_t)(b * SS + q0 + lrow)) * HID + h * HD + dch;
    const float* kg = k + ((size_t)(b * SS + k0 + lrow)) * HID + h * HD + dch;
#pragma unroll
    for (int c = 0; c < 16; c += 4) {
        const float4 a = *(const float4*)(qg + c);
        Qs[dch+c+0][lrow] = a.x; Qs[dch+c+1][lrow] = a.y;
        Qs[dch+c+2][lrow] = a.z; Qs[dch+c+3][lrow] = a.w;
        const float4 w = *(const float4*)(kg + c);
        Ks[dch+c+0][lrow] = w.x; Ks[dch+c+1][lrow] = w.y;
        Ks[dch+c+2][lrow] = w.z; Ks[dch+c+3][lrow] = w.w;
    }
    __syncthreads();

    const int tx = tid & 15, ty = tid >> 4;
    float acc[4][4];
#pragma unroll
    for (int i = 0; i < 4; i++)
#pragma unroll
        for (int j = 0; j < 4; j++) acc[i][j] = 0.f;

#pragma unroll
    for (int d = 0; d < 64; d++) {
        float qr[4], kr[4];
#pragma unroll
        for (int i = 0; i < 4; i++) qr[i] = Qs[d][ty * 4 + i];
        *(float4*)kr = *(const float4*)&Ks[d][tx * 4];
#pragma unroll
        for (int i = 0; i < 4; i++)
#pragma unroll
            for (int j = 0; j < 4; j++)
                acc[i][j] += qr[i] * kr[j];
    }

#pragma unroll
    for (int i = 0; i < 4; i++) {
        const int qrow = q0 + ty * 4 + i;
        const float* mr = mask + ((size_t)b * SS + qrow) * SS + k0 + tx * 4;
        float* sr = scores + ((size_t)bh * SS + qrow) * SS + k0 + tx * 4;
#pragma unroll
        for (int j = 0; j < 4; j++)
            sr[j] = acc[i][j] * 0.125f + mr[j];
    }
}

// ---------------------------------------------------------------------------
// Row softmax over 1024 keys (in place). one block per row
// ---------------------------------------------------------------------------
__global__ void __launch_bounds__(256) softmax_kernel(float* __restrict__ sc)
{
    const size_t row = blockIdx.x;
    float* p = sc + row * (size_t)SS;
    const int tid = threadIdx.x;

    float v[4];
    float m = -INFINITY;
#pragma unroll
    for (int i = 0; i < 4; i++) { v[i] = p[tid + i * 256]; m = fmaxf(m, v[i]); }
#pragma unroll
    for (int o = 16; o; o >>= 1) m = fmaxf(m, __shfl_xor_sync(0xffffffffu, m, o));
    __shared__ float red[8];
    if ((tid & 31) == 0) red[tid >> 5] = m;
    __syncthreads();
    if (tid < 32) {
        m = (tid < 8) ? red[tid] : -INFINITY;
#pragma unroll
        for (int o = 4; o; o >>= 1) m = fmaxf(m, __shfl_xor_sync(0xffffffffu, m, o));
        if (tid == 0) red[0] = m;
    }
    __syncthreads();
    m = red[0];

    float s = 0.f;
#pragma unroll
    for (int i = 0; i < 4; i++) { v[i] = expf(v[i] - m); s += v[i]; }
#pragma unroll
    for (int o = 16; o; o >>= 1) s += __shfl_xor_sync(0xffffffffu, s, o);
    __shared__ float red2[8];
    if ((tid & 31) == 0) red2[tid >> 5] = s;
    __syncthreads();
    if (tid < 32) {
        s = (tid < 8) ? red2[tid] : 0.f;
#pragma unroll
        for (int o = 4; o; o >>= 1) s += __shfl_xor_sync(0xffffffffu, s, o);
        if (tid == 0) red2[0] = s;
    }
    __syncthreads();
    const float inv = 1.f / red2[0];
#pragma unroll
    for (int i = 0; i < 4; i++) p[tid + i * 256] = v[i] * inv;
}

// ---------------------------------------------------------------------------
// ctx[bh, q, :] = P[bh, q, :] @ V[bh, :, :]  ; one block = 64 q x 64 d
// grid: (S/64 qtiles, B*NH)
// ---------------------------------------------------------------------------
__global__ void __launch_bounds__(256) attn_ctx_kernel(
    const float* __restrict__ scores, const float* __restrict__ v,
    float* __restrict__ ctx)
{
    const int bh = blockIdx.y;
    const int b = bh >> 5, h = bh & 31;
    const int q0 = blockIdx.x * 64;

    __shared__ float Ps[64][68];  // [q][k]
    __shared__ float Vs[64][68];  // [k][d]

    const int tid  = threadIdx.x;
    const int tx   = tid & 15, ty = tid >> 4;
    const int lrow = tid & 63;
    const int cch  = (tid >> 6) * 16;

    float acc[4][4];
#pragma unroll
    for (int i = 0; i < 4; i++)
#pragma unroll
        for (int j = 0; j < 4; j++) acc[i][j] = 0.f;

    for (int kt = 0; kt < SS; kt += 64) {
        const float* pg = scores + ((size_t)bh * SS + q0 + lrow) * SS + kt + cch;
        const float* vg = v + ((size_t)(b * SS + kt + lrow)) * HID + h * HD + cch;
#pragma unroll
        for (int c = 0; c < 16; c += 4) {
            *(float4*)&Ps[lrow][cch + c] = *(const float4*)(pg + c);
            *(float4*)&Vs[lrow][cch + c] = *(const float4*)(vg + c);
        }
        __syncthreads();
#pragma unroll
        for (int kk = 0; kk < 64; kk++) {
            float pr[4];
#pragma unroll
            for (int i = 0; i < 4; i++) pr[i] = Ps[ty * 4 + i][kk];
            const float4 vv = *(const float4*)&Vs[kk][tx * 4];
#pragma unroll
            for (int i = 0; i < 4; i++) {
                acc[i][0] += pr[i] * vv.x;
                acc[i][1] += pr[i] * vv.y;
                acc[i][2] += pr[i] * vv.z;
                acc[i][3] += pr[i] * vv.w;
            }
        }
        __syncthreads();
    }

#pragma unroll
    for (int i = 0; i < 4; i++) {
        float* cr = ctx + ((size_t)(b * SS + q0 + ty * 4 + i)) * HID + h * HD + tx * 4;
#pragma unroll
        for (int j = 0; j < 4; j++) cr[j] = acc[i][j];
    }
}

// ---------------------------------------------------------------------------
// SwiGLU activation: gate = silu(gate) * up   (elementwise, float4)
// ---------------------------------------------------------------------------
__global__ void __launch_bounds__(256) silu_mul_kernel(
    float* __restrict__ gate, const float* __restrict__ up)
{
    const size_t i = ((size_t)blockIdx.x * blockDim.x + threadIdx.x) * 4;
    float4 g = *(float4*)(gate + i);
    const float4 u = *(const float4*)(up + i);
    g.x = g.x / (1.f + expf(-g.x)) * u.x;
    g.y = g.y / (1.f + expf(-g.y)) * u.y;
    g.z = g.z / (1.f + expf(-g.z)) * u.z;
    g.w = g.w / (1.f + expf(-g.w)) * u.w;
    *(float4*)(gate + i) = g;
}

// ---------------------------------------------------------------------------
// Launch
// ---------------------------------------------------------------------------
extern "C" void kernel_launch(void* const* d_in, const int* in_sizes, int n_in,
                              void* d_out, int out_size)
{
    const float* hidden = (const float*)d_in[0];
    const float* memory = (const float*)d_in[1];
    const float* mask   = (const float*)d_in[2];
    const int*   pos    = (const int*)  d_in[3];
    const float* Wq     = (const float*)d_in[4];
    const float* Wk     = (const float*)d_in[5];
    const float* Wv     = (const float*)d_in[6];
    const float* Wo     = (const float*)d_in[7];
    const float* ln1w   = (const float*)d_in[8];
    const float* ln1b   = (const float*)d_in[9];
    const float* ln2w   = (const float*)d_in[10];
    const float* ln2b   = (const float*)d_in[11];
    const float* gw     = (const float*)d_in[12];
    const float* uw     = (const float*)d_in[13];
    const float* dw     = (const float*)d_in[14];
    float* out = (float*)d_out;

    float *xln, *q, *k, *v, *sc, *ctx, *h, *yln, *gate, *up;
    cudaGetSymbolAddress((void**)&xln,  g_xln);
    cudaGetSymbolAddress((void**)&q,    g_q);
    cudaGetSymbolAddress((void**)&k,    g_k);
    cudaGetSymbolAddress((void**)&v,    g_v);
    cudaGetSymbolAddress((void**)&sc,   g_sc);
    cudaGetSymbolAddress((void**)&ctx,  g_ctx);
    cudaGetSymbolAddress((void**)&h,    g_h);
    cudaGetSymbolAddress((void**)&yln,  g_yln);
    cudaGetSymbolAddress((void**)&gate, g_gate);
    cudaGetSymbolAddress((void**)&up,   g_up);

    // 1) LN1
    layernorm_kernel<<<TT, 256>>>(hidden, ln1w, ln1b, xln);

    // 2) Q/K/V projections (Q from LN(x), K/V from memory)
    dim3 g2k(HID / 128, TT / 128);
    sgemm_nt_kernel<<<g2k, 256>>>(xln,    Wq, nullptr, q, TT, HID, HID);
    sgemm_nt_kernel<<<g2k, 256>>>(memory, Wk, nullptr, k, TT, HID, HID);
    sgemm_nt_kernel<<<g2k, 256>>>(memory, Wv, nullptr, v, TT, HID, HID);

    // 3) RoPE (first 16 dims of each head)
    rope_kernel<<<(TT * NH * 8) / 256, 256>>>(q, k, pos);

    // 4) scores = QK^T/8 + mask ; softmax ; ctx = P V
    attn_scores_kernel<<<dim3(SS / 64, SS / 64, BB * NH), 256>>>(q, k, mask, sc);
    softmax_kernel<<<BB * NH * SS, 256>>>(sc);
    attn_ctx_kernel<<<dim3(SS / 64, BB * NH), 256>>>(sc, v, ctx);

    // 5) O projection + residual
    sgemm_nt_kernel<<<g2k, 256>>>(ctx, Wo, hidden, h, TT, HID, HID);

    // 6) LN2
    layernorm_kernel<<<TT, 256>>>(h, ln2w, ln2b, yln);

    // 7) SwiGLU MLP + residual
    dim3 gff(DFF / 128, TT / 128);
    sgemm_nt_kernel<<<gff, 256>>>(yln, gw, nullptr, gate, TT, DFF, HID);
    sgemm_nt_kernel<<<gff, 256>>>(yln, uw, nullptr, up,   TT, DFF, HID);
    silu_mul_kernel<<<((size_t)TT * DFF / 4) / 256, 256>>>(gate, up);
    sgemm_nt_kernel<<<g2k, 256>>>(gate, dw, h, out, TT, HID, DFF);
}

// round 3
// speedup vs baseline: 1.6145x; 1.6145x over previous
#include <cuda_runtime.h>
#include <cuda_bf16.h>
#include <math.h>
#include <stdint.h>

// ---------------------------------------------------------------------------
// Problem constants
// ---------------------------------------------------------------------------
#define BB     2
#define SS     1024
#define TT     (BB*SS)        // 2048 tokens
#define HID    2048
#define NH     32
#define HD     64
#define ROT    16
#define DFF    8192
#define LN_EPS 1e-5f

// ---------------------------------------------------------------------------
// Static scratch (no allocations allowed)
// ---------------------------------------------------------------------------
__device__ float g_xln[(size_t)TT * HID];
__device__ float g_q  [(size_t)TT * HID];
__device__ float g_k  [(size_t)TT * HID];
__device__ float g_v  [(size_t)TT * HID];
__device__ float g_sc [(size_t)BB * NH * SS * SS];   // 256 MB scores
__device__ float g_ctx[(size_t)TT * HID];
__device__ float g_h  [(size_t)TT * HID];
__device__ float g_yln[(size_t)TT * HID];
__device__ float g_gate[(size_t)TT * DFF];
__device__ float g_up [(size_t)TT * DFF];

// bf16 3-split scratch
__device__ __nv_bfloat16 g_a3[(size_t)2048 * 24576];
__device__ __nv_bfloat16 g_b3[(size_t)8192 * 6144];

// ---------------------------------------------------------------------------
// helpers
// ---------------------------------------------------------------------------
__device__ __forceinline__ uint32_t smem_u32(const void* p) {
    uint32_t a;
    asm("{ .reg .u64 t; cvta.to.shared.u64 t, %1; cvt.u32.u64 %0, t; }"
        : "=r"(a) : "l"(p));
    return a;
}

#define CP_ASYNC16(sa, ga) \
    asm volatile("cp.async.cg.shared.global [%0], [%1], 16;" :: "r"(sa), "l"(ga))
#define CP_COMMIT() asm volatile("cp.async.commit_group;")
#define CP_WAIT1()  asm volatile("cp.async.wait_group 1;")

#define LDSM4(r, addr) \
    asm volatile("ldmatrix.sync.aligned.m8n8.x4.shared.b16 {%0,%1,%2,%3}, [%4];" \
        : "=r"((r)[0]), "=r"((r)[1]), "=r"((r)[2]), "=r"((r)[3]) : "r"(addr))

#define MMA16816(d, a, b0, b1) \
    asm volatile("mma.sync.aligned.m16n8k16.row.col.f32.bf16.bf16.f32 " \
        "{%0,%1,%2,%3}, {%4,%5,%6,%7}, {%8,%9}, {%0,%1,%2,%3};" \
        : "+f"((d)[0]), "+f"((d)[1]), "+f"((d)[2]), "+f"((d)[3]) \
        : "r"((a)[0]), "r"((a)[1]), "r"((a)[2]), "r"((a)[3]), "r"(b0), "r"(b1))

// ---------------------------------------------------------------------------
// HMMA bf16 GEMM:  C[M,N] = A3[M,K3] * B3[N,K3]^T (+ optional addend)
// 128x128 tile, BK=64 (128B rows, SW128-xor swizzle), 3-stage cp.async,
// 256 threads = 8 warps (2M x 4N), warp tile 64x32, mma m16n8k16 bf16.
// ---------------------------------------------------------------------------
#define GSTAGES      3
#define GTILE_BYTES  16384                     // 128 rows * 128B
#define GSTAGE_BYTES (2 * GTILE_BYTES)         // A + B
#define GEMM_DSMEM   (GSTAGES * GSTAGE_BYTES)  // 96 KB

__global__ void __launch_bounds__(256, 2) gemm3_kernel(
    const __nv_bfloat16* __restrict__ A, const __nv_bfloat16* __restrict__ B,
    const float* __restrict__ add, float* __restrict__ C,
    int M, int N, int K3)
{
    extern __shared__ __align__(128) char smem[];
    const uint32_t smem_base = smem_u32(smem);

    const int tid  = threadIdx.x;
    const int lane = tid & 31;
    const int warp = tid >> 5;
    const int wm = warp >> 2;        // 0..1
    const int wn = warp & 3;         // 0..3
    const int bx = blockIdx.x, by = blockIdx.y;
    const int nk = K3 >> 6;

    // per-thread load geometry (4 chunks per tile per thread)
    int lrow[4], lswz[4];
#pragma unroll
    for (int p = 0; p < 4; p++) {
        const int id = p * 256 + tid;          // 0..1023
        const int row = id >> 3;
        const int c   = id & 7;
        lrow[p] = row;
        lswz[p] = row * 128 + ((c ^ (row & 7)) << 4);
    }
    const __nv_bfloat16* Abase = A + (size_t)(by * 128) * K3;
    const __nv_bfloat16* Bbase = B + (size_t)(bx * 128) * K3;

    float acc[4][4][4];
#pragma unroll
    for (int i = 0; i < 4; i++)
#pragma unroll
        for (int j = 0; j < 4; j++)
#pragma unroll
            for (int r = 0; r < 4; r++) acc[i][j][r] = 0.f;

    auto load_tile = [&](int ks, int buf) {
        const uint32_t sa = smem_base + buf * GSTAGE_BYTES;
        const uint32_t sb = sa + GTILE_BYTES;
        const int koff = ks * 64;
#pragma unroll
        for (int p = 0; p < 4; p++) {
            const int id = p * 256 + tid;
            const int c  = id & 7;
            const __nv_bfloat16* ga = Abase + (size_t)lrow[p] * K3 + koff + c * 8;
            const __nv_bfloat16* gb = Bbase + (size_t)lrow[p] * K3 + koff + c * 8;
            CP_ASYNC16(sa + lswz[p], ga);
            CP_ASYNC16(sb + lswz[p], gb);
        }
    };

    // prefetch stages 0,1
    load_tile(0, 0); CP_COMMIT();
    load_tile(1, 1); CP_COMMIT();

    for (int ks = 0; ks < nk; ks++) {
        CP_WAIT1();
        __syncthreads();
        if (ks + 2 < nk) load_tile(ks + 2, (ks + 2) % GSTAGES);
        CP_COMMIT();

        const int buf = ks % GSTAGES;
        const uint32_t sa = smem_base + buf * GSTAGE_BYTES;
        const uint32_t sb = sa + GTILE_BYTES;

#pragma unroll
        for (int kk = 0; kk < 4; kk++) {
            uint32_t ra[4][4];
#pragma unroll
            for (int mt = 0; mt < 4; mt++) {
                const int row = wm * 64 + mt * 16 + (lane & 15);
                const int ch  = kk * 2 + (lane >> 4);
                LDSM4(ra[mt], sa + row * 128 + ((ch ^ (row & 7)) << 4));
            }
            uint32_t rb[2][4];
#pragma unroll
            for (int pr = 0; pr < 2; pr++) {
                const int n  = wn * 32 + pr * 16 + (lane & 7) + ((lane >> 4) << 3);
                const int ch = kk * 2 + ((lane >> 3) & 1);
                LDSM4(rb[pr], sb + n * 128 + ((ch ^ (n & 7)) << 4));
            }
#pragma unroll
            for (int mt = 0; mt < 4; mt++)
#pragma unroll
                for (int nt = 0; nt < 4; nt++)
                    MMA16816(acc[mt][nt], ra[mt],
                             rb[nt >> 1][(nt & 1) * 2], rb[nt >> 1][(nt & 1) * 2 + 1]);
        }
        __syncthreads();
    }

    // epilogue
    const int r0 = lane >> 2;
    const int c0 = (lane & 3) * 2;
#pragma unroll
    for (int mt = 0; mt < 4; mt++) {
#pragma unroll
        for (int half = 0; half < 2; half++) {
            const int row = by * 128 + wm * 64 + mt * 16 + r0 + half * 8;
            float* Cr = C + (size_t)row * N + bx * 128 + wn * 32;
            const float* Ar = add ? add + (size_t)row * N + bx * 128 + wn * 32 : nullptr;
#pragma unroll
            for (int nt = 0; nt < 4; nt++) {
                float2 o;
                o.x = acc[mt][nt][half * 2];
                o.y = acc[mt][nt][half * 2 + 1];
                if (Ar) {
                    const float2 av = *(const float2*)(Ar + nt * 8 + c0);
                    o.x += av.x; o.y += av.y;
                }
                *(float2*)(Cr + nt * 8 + c0) = o;
            }
        }
    }
}

// ---------------------------------------------------------------------------
// fp32 -> bf16 3-split. brole=0: [hi|lo|hi]  brole=1: [hi|hi|lo]
// ---------------------------------------------------------------------------
__global__ void __launch_bounds__(256) split3_kernel(
    const float* __restrict__ X, __nv_bfloat16* __restrict__ Y, int C, int brole)
{
    const size_t e = ((size_t)blockIdx.x * 256 + threadIdx.x) * 4;
    const size_t r = e / (size_t)C;
    const int   c = (int)(e - r * (size_t)C);
    const float4 v = *(const float4*)(X + e);
    float xs[4] = {v.x, v.y, v.z, v.w};
    uint32_t hpx = 0, hpy = 0, lpx = 0, lpy = 0;
#pragma unroll
    for (int j = 0; j < 4; j++) {
        __nv_bfloat16 h = __float2bfloat16(xs[j]);
        __nv_bfloat16 l = __float2bfloat16(xs[j] - __bfloat162float(h));
        uint32_t hu = (uint32_t)__bfloat16_as_ushort(h);
        uint32_t lu = (uint32_t)__bfloat16_as_ushort(l);
        if (j < 2) { hpx |= hu << (16 * j); lpx |= lu << (16 * j); }
        else       { hpy |= hu << (16 * (j - 2)); lpy |= lu << (16 * (j - 2)); }
    }
    uint2 hp = make_uint2(hpx, hpy), lp = make_uint2(lpx, lpy);
    __nv_bfloat16* yb = Y + r * (size_t)(3 * C) + c;
    *(uint2*)(yb)         = hp;
    *(uint2*)(yb + C)     = brole ? hp : lp;
    *(uint2*)(yb + 2 * C) = brole ? lp : hp;
}

// ---------------------------------------------------------------------------
// LayerNorm: one block (256 thr) per token, 2048 features
// ---------------------------------------------------------------------------
__global__ void __launch_bounds__(256) layernorm_kernel(
    const float* __restrict__ x, const float* __restrict__ w,
    const float* __restrict__ b, float* __restrict__ out)
{
    const int t   = blockIdx.x;
    const int tid = threadIdx.x;
    const float* xr = x + (size_t)t * HID;

    float v[8];
    float s = 0.f, s2 = 0.f;
#pragma unroll
    for (int i = 0; i < 8; i++) {
        v[i] = xr[tid + i * 256];
        s  += v[i];
        s2 += v[i] * v[i];
    }
#pragma unroll
    for (int o = 16; o; o >>= 1) {
        s  += __shfl_xor_sync(0xffffffffu, s,  o);
        s2 += __shfl_xor_sync(0xffffffffu, s2, o);
    }
    __shared__ float ss[8], ss2[8];
    if ((tid & 31) == 0) { ss[tid >> 5] = s; ss2[tid >> 5] = s2; }
    __syncthreads();
    if (tid < 32) {
        s  = (tid < 8) ? ss [tid] : 0.f;
        s2 = (tid < 8) ? ss2[tid] : 0.f;
#pragma unroll
        for (int o = 4; o; o >>= 1) {
            s  += __shfl_xor_sync(0xffffffffu, s,  o);
            s2 += __shfl_xor_sync(0xffffffffu, s2, o);
        }
        if (tid == 0) { ss[0] = s; ss2[0] = s2; }
    }
    __syncthreads();
    const float mean = ss[0] * (1.f / HID);
    const float var  = ss2[0] * (1.f / HID) - mean * mean;
    const float rstd = rsqrtf(var + LN_EPS);
    float* orow = out + (size_t)t * HID;
#pragma unroll
    for (int i = 0; i < 8; i++) {
        const int idx = tid + i * 256;
        orow[idx] = (v[i] - mean) * rstd * w[idx] + b[idx];
    }
}

// ---------------------------------------------------------------------------
// Partial RoPE on first 16 dims of each head (q and k), pairs (i, i+8)
// ---------------------------------------------------------------------------
__global__ void __launch_bounds__(256) rope_kernel(
    float* __restrict__ q, float* __restrict__ k, const int* __restrict__ pos_ids)
{
    const int idx = blockIdx.x * blockDim.x + threadIdx.x;
    if (idx >= TT * NH * 8) return;
    const int i = idx & 7;
    const int h = (idx >> 3) & 31;
    const int t = idx >> 8;
    const int b = t / SS, s = t % SS;
    const int pos = pos_ids[b * SS + s];

    const float freq = powf(10000.0f, -(2.0f * (float)i) / (float)ROT);
    const float ang  = (float)pos * freq;
    float c, si;
    sincosf(ang, &si, &c);

    const size_t base = (size_t)t * HID + h * HD;
    float q0 = q[base + i], q1 = q[base + i + 8];
    q[base + i]     = q0 * c - q1 * si;
    q[base + i + 8] = q1 * c + q0 * si;
    float k0 = k[base + i], k1 = k[base + i + 8];
    k[base + i]     = k0 * c - k1 * si;
    k[base + i + 8] = k1 * c + k0 * si;
}

// ---------------------------------------------------------------------------
// Attention scores: S[bh, q, k] = (Q . K)/8 + mask ; 64x64 tile per block
// ---------------------------------------------------------------------------
__global__ void __launch_bounds__(256) attn_scores_kernel(
    const float* __restrict__ q, const float* __restrict__ k,
    const float* __restrict__ mask, float* __restrict__ scores)
{
    const int bh = blockIdx.z;
    const int b = bh >> 5, h = bh & 31;
    const int q0 = blockIdx.y * 64, k0 = blockIdx.x * 64;

    __shared__ float Qs[64][68];
    __shared__ float Ks[64][68];

    const int tid  = threadIdx.x;
    const int lrow = tid & 63;
    const int dch  = (tid >> 6) * 16;

    const float* qg = q + ((size_t)(b * SS + q0 + lrow)) * HID + h * HD + dch;
    const float* kg = k + ((size_t)(b * SS + k0 + lrow)) * HID + h * HD + dch;
#pragma unroll
    for (int c = 0; c < 16; c += 4) {
        const float4 a = *(const float4*)(qg + c);
        Qs[dch+c+0][lrow] = a.x; Qs[dch+c+1][lrow] = a.y;
        Qs[dch+c+2][lrow] = a.z; Qs[dch+c+3][lrow] = a.w;
        const float4 w = *(const float4*)(kg + c);
        Ks[dch+c+0][lrow] = w.x; Ks[dch+c+1][lrow] = w.y;
        Ks[dch+c+2][lrow] = w.z; Ks[dch+c+3][lrow] = w.w;
    }
    __syncthreads();

    const int tx = tid & 15, ty = tid >> 4;
    float acc[4][4];
#pragma unroll
    for (int i = 0; i < 4; i++)
#pragma unroll
        for (int j = 0; j < 4; j++) acc[i][j] = 0.f;

#pragma unroll
    for (int d = 0; d < 64; d++) {
        float qr[4], kr[4];
#pragma unroll
        for (int i = 0; i < 4; i++) qr[i] = Qs[d][ty * 4 + i];
        *(float4*)kr = *(const float4*)&Ks[d][tx * 4];
#pragma unroll
        for (int i = 0; i < 4; i++)
#pragma unroll
            for (int j = 0; j < 4; j++)
                acc[i][j] += qr[i] * kr[j];
    }

#pragma unroll
    for (int i = 0; i < 4; i++) {
        const int qrow = q0 + ty * 4 + i;
        const float* mr = mask + ((size_t)b * SS + qrow) * SS + k0 + tx * 4;
        float* sr = scores + ((size_t)bh * SS + qrow) * SS + k0 + tx * 4;
#pragma unroll
        for (int j = 0; j < 4; j++)
            sr[j] = acc[i][j] * 0.125f + mr[j];
    }
}

// ---------------------------------------------------------------------------
// Row softmax over 1024 keys (in place). one block per row
// ---------------------------------------------------------------------------
__global__ void __launch_bounds__(256) softmax_kernel(float* __restrict__ sc)
{
    const size_t row = blockIdx.x;
    float* p = sc + row * (size_t)SS;
    const int tid = threadIdx.x;

    float v[4];
    float m = -INFINITY;
#pragma unroll
    for (int i = 0; i < 4; i++) { v[i] = p[tid + i * 256]; m = fmaxf(m, v[i]); }
#pragma unroll
    for (int o = 16; o; o >>= 1) m = fmaxf(m, __shfl_xor_sync(0xffffffffu, m, o));
    __shared__ float red[8];
    if ((tid & 31) == 0) red[tid >> 5] = m;
    __syncthreads();
    if (tid < 32) {
        m = (tid < 8) ? red[tid] : -INFINITY;
#pragma unroll
        for (int o = 4; o; o >>= 1) m = fmaxf(m, __shfl_xor_sync(0xffffffffu, m, o));
        if (tid == 0) red[0] = m;
    }
    __syncthreads();
    m = red[0];

    float s = 0.f;
#pragma unroll
    for (int i = 0; i < 4; i++) { v[i] = expf(v[i] - m); s += v[i]; }
#pragma unroll
    for (int o = 16; o; o >>= 1) s += __shfl_xor_sync(0xffffffffu, s, o);
    __shared__ float red2[8];
    if ((tid & 31) == 0) red2[tid >> 5] = s;
    __syncthreads();
    if (tid < 32) {
        s = (tid < 8) ? red2[tid] : 0.f;
#pragma unroll
        for (int o = 4; o; o >>= 1) s += __shfl_xor_sync(0xffffffffu, s, o);
        if (tid == 0) red2[0] = s;
    }
    __syncthreads();
    const float inv = 1.f / red2[0];
#pragma unroll
    for (int i = 0; i < 4; i++) p[tid + i * 256] = v[i] * inv;
}

// ---------------------------------------------------------------------------
// ctx = P @ V ; one block = 64 q x 64 d
// ---------------------------------------------------------------------------
__global__ void __launch_bounds__(256) attn_ctx_kernel(
    const float* __restrict__ scores, const float* __restrict__ v,
    float* __restrict__ ctx)
{
    const int bh = blockIdx.y;
    const int b = bh >> 5, h = bh & 31;
    const int q0 = blockIdx.x * 64;

    __shared__ float Ps[64][68];
    __shared__ float Vs[64][68];

    const int tid  = threadIdx.x;
    const int tx   = tid & 15, ty = tid >> 4;
    const int lrow = tid & 63;
    const int cch  = (tid >> 6) * 16;

    float acc[4][4];
#pragma unroll
    for (int i = 0; i < 4; i++)
#pragma unroll
        for (int j = 0; j < 4; j++) acc[i][j] = 0.f;

    for (int kt = 0; kt < SS; kt += 64) {
        const float* pg = scores + ((size_t)bh * SS + q0 + lrow) * SS + kt + cch;
        const float* vg = v + ((size_t)(b * SS + kt + lrow)) * HID + h * HD + cch;
#pragma unroll
        for (int c = 0; c < 16; c += 4) {
            *(float4*)&Ps[lrow][cch + c] = *(const float4*)(pg + c);
            *(float4*)&Vs[lrow][cch + c] = *(const float4*)(vg + c);
        }
        __syncthreads();
#pragma unroll
        for (int kk = 0; kk < 64; kk++) {
            float pr[4];
#pragma unroll
            for (int i = 0; i < 4; i++) pr[i] = Ps[ty * 4 + i][kk];
            const float4 vv = *(const float4*)&Vs[kk][tx * 4];
#pragma unroll
            for (int i = 0; i < 4; i++) {
                acc[i][0] += pr[i] * vv.x;
                acc[i][1] += pr[i] * vv.y;
                acc[i][2] += pr[i] * vv.z;
                acc[i][3] += pr[i] * vv.w;
            }
        }
        __syncthreads();
    }

#pragma unroll
    for (int i = 0; i < 4; i++) {
        float* cr = ctx + ((size_t)(b * SS + q0 + ty * 4 + i)) * HID + h * HD + tx * 4;
#pragma unroll
        for (int j = 0; j < 4; j++) cr[j] = acc[i][j];
    }
}

// ---------------------------------------------------------------------------
// SwiGLU activation: gate = silu(gate) * up
// ---------------------------------------------------------------------------
__global__ void __launch_bounds__(256) silu_mul_kernel(
    float* __restrict__ gate, const float* __restrict__ up)
{
    const size_t i = ((size_t)blockIdx.x * blockDim.x + threadIdx.x) * 4;
    float4 g = *(float4*)(gate + i);
    const float4 u = *(const float4*)(up + i);
    g.x = g.x / (1.f + expf(-g.x)) * u.x;
    g.y = g.y / (1.f + expf(-g.y)) * u.y;
    g.z = g.z / (1.f + expf(-g.z)) * u.z;
    g.w = g.w / (1.f + expf(-g.w)) * u.w;
    *(float4*)(gate + i) = g;
}

// ---------------------------------------------------------------------------
// Launch
// ---------------------------------------------------------------------------
extern "C" void kernel_launch(void* const* d_in, const int* in_sizes, int n_in,
                              void* d_out, int out_size)
{
    const float* hidden = (const float*)d_in[0];
    const float* memory = (const float*)d_in[1];
    const float* mask   = (const float*)d_in[2];
    const int*   pos    = (const int*)  d_in[3];
    const float* Wq     = (const float*)d_in[4];
    const float* Wk     = (const float*)d_in[5];
    const float* Wv     = (const float*)d_in[6];
    const float* Wo     = (const float*)d_in[7];
    const float* ln1w   = (const float*)d_in[8];
    const float* ln1b   = (const float*)d_in[9];
    const float* ln2w   = (const float*)d_in[10];
    const float* ln2b   = (const float*)d_in[11];
    const float* gw     = (const float*)d_in[12];
    const float* uw     = (const float*)d_in[13];
    const float* dw     = (const float*)d_in[14];
    float* out = (float*)d_out;

    float *xln, *q, *k, *v, *sc, *ctx, *h, *yln, *gate, *up;
    __nv_bfloat16 *a3, *b3;
    cudaGetSymbolAddress((void**)&xln,  g_xln);
    cudaGetSymbolAddress((void**)&q,    g_q);
    cudaGetSymbolAddress((void**)&k,    g_k);
    cudaGetSymbolAddress((void**)&v,    g_v);
    cudaGetSymbolAddress((void**)&sc,   g_sc);
    cudaGetSymbolAddress((void**)&ctx,  g_ctx);
    cudaGetSymbolAddress((void**)&h,    g_h);
    cudaGetSymbolAddress((void**)&yln,  g_yln);
    cudaGetSymbolAddress((void**)&gate, g_gate);
    cudaGetSymbolAddress((void**)&up,   g_up);
    cudaGetSymbolAddress((void**)&a3,   g_a3);
    cudaGetSymbolAddress((void**)&b3,   g_b3);

    cudaFuncSetAttribute(gemm3_kernel,
                         cudaFuncAttributeMaxDynamicSharedMemorySize, GEMM_DSMEM);

    auto gemm = [&](const __nv_bfloat16* A, const __nv_bfloat16* B,
                    const float* add, float* C, int M, int N, int K3) {
        gemm3_kernel<<<dim3(N / 128, M / 128), 256, GEMM_DSMEM>>>(A, B, add, C, M, N, K3);
    };
    auto split = [&](const float* X, __nv_bfloat16* Y, int R, int C, int brole) {
        split3_kernel<<<(unsigned)((size_t)R * C / 1024), 256>>>(X, Y, C, brole);
    };

    // 1) LN1
    layernorm_kernel<<<TT, 256>>>(hidden, ln1w, ln1b, xln);

    // 2) Q projection
    split(xln, a3, TT, HID, 0);
    split(Wq,  b3, HID, HID, 1);
    gemm(a3, b3, nullptr, q, TT, HID, 3 * HID);

    // 3) K/V projections from memory
    split(memory, a3, TT, HID, 0);
    split(Wk, b3, HID, HID, 1);
    gemm(a3, b3, nullptr, k, TT, HID, 3 * HID);
    split(Wv, b3, HID, HID, 1);
    gemm(a3, b3, nullptr, v, TT, HID, 3 * HID);

    // 4) RoPE
    rope_kernel<<<(TT * NH * 8) / 256, 256>>>(q, k, pos);

    // 5) attention (fp32)
    attn_scores_kernel<<<dim3(SS / 64, SS / 64, BB * NH), 256>>>(q, k, mask, sc);
    softmax_kernel<<<BB * NH * SS, 256>>>(sc);
    attn_ctx_kernel<<<dim3(SS / 64, BB * NH), 256>>>(sc, v, ctx);

    // 6) O projection + residual
    split(ctx, a3, TT, HID, 0);
    split(Wo,  b3, HID, HID, 1);
    gemm(a3, b3, hidden, h, TT, HID, 3 * HID);

    // 7) LN2
    layernorm_kernel<<<TT, 256>>>(h, ln2w, ln2b, yln);

    // 8) SwiGLU MLP + residual
    split(yln, a3, TT, HID, 0);
    split(gw, b3, DFF, HID, 1);
    gemm(a3, b3, nullptr, gate, TT, DFF, 3 * HID);
    split(uw, b3, DFF, HID, 1);
    gemm(a3, b3, nullptr, up, TT, DFF, 3 * HID);
    silu_mul_kernel<<<(unsigned)(((size_t)TT * DFF / 4) / 256), 256>>>(gate, up);
    split(gate, a3, TT, DFF, 0);
    split(dw,   b3, HID, DFF, 1);
    gemm(a3, b3, h, out, TT, HID, 3 * DFF);
}

// round 4
// speedup vs baseline: 2.9217x; 1.8097x over previous
#include <cuda_runtime.h>
#include <cuda_bf16.h>
#include <math.h>
#include <stdint.h>

// ---------------------------------------------------------------------------
// Problem constants
// ---------------------------------------------------------------------------
#define BB     2
#define SS     1024
#define TT     (BB*SS)        // 2048 tokens
#define HID    2048
#define NH     32
#define HD     64
#define ROT    16
#define DFF    8192
#define LN_EPS 1e-5f

// ---------------------------------------------------------------------------
// Static scratch (no allocations allowed)
// ---------------------------------------------------------------------------
__device__ float g_xln[(size_t)TT * HID];
__device__ float g_q  [(size_t)TT * HID];
__device__ float g_k  [(size_t)TT * HID];
__device__ float g_v  [(size_t)TT * HID];
__device__ float g_h  [(size_t)TT * HID];
__device__ float g_yln[(size_t)TT * HID];
__device__ float g_up [(size_t)TT * DFF];

// bf16 3-split scratch
__device__ __nv_bfloat16 g_a3[(size_t)TT * 24576];     // A operand splits / ctx split
__device__ __nv_bfloat16 g_b3[(size_t)DFF * 6144];     // B operand splits
__device__ __nv_bfloat16 g_c3[(size_t)TT * 24576];     // activated-gate split

// ---------------------------------------------------------------------------
// helpers
// ---------------------------------------------------------------------------
__device__ __forceinline__ uint32_t smem_u32(const void* p) {
    uint32_t a;
    asm("{ .reg .u64 t; cvta.to.shared.u64 t, %1; cvt.u32.u64 %0, t; }"
        : "=r"(a) : "l"(p));
    return a;
}

#define CP_ASYNC16(sa, ga) \
    asm volatile("cp.async.cg.shared.global [%0], [%1], 16;" :: "r"(sa), "l"(ga))
#define CP_COMMIT() asm volatile("cp.async.commit_group;")
#define CP_WAIT1()  asm volatile("cp.async.wait_group 1;")

#define LDSM4(r, addr) \
    asm volatile("ldmatrix.sync.aligned.m8n8.x4.shared.b16 {%0,%1,%2,%3}, [%4];" \
        : "=r"((r)[0]), "=r"((r)[1]), "=r"((r)[2]), "=r"((r)[3]) : "r"(addr))

#define MMA16816(d, a, b0, b1) \
    asm volatile("mma.sync.aligned.m16n8k16.row.col.f32.bf16.bf16.f32 " \
        "{%0,%1,%2,%3}, {%4,%5,%6,%7}, {%8,%9}, {%0,%1,%2,%3};" \
        : "+f"((d)[0]), "+f"((d)[1]), "+f"((d)[2]), "+f"((d)[3]) \
        : "r"((a)[0]), "r"((a)[1]), "r"((a)[2]), "r"((a)[3]), "r"(b0), "r"(b1))

__device__ __forceinline__ uint32_t pack_bf2(float a, float b) {
    uint32_t h0 = (uint32_t)__bfloat16_as_ushort(__float2bfloat16(a));
    uint32_t h1 = (uint32_t)__bfloat16_as_ushort(__float2bfloat16(b));
    return h0 | (h1 << 16);
}

// ---------------------------------------------------------------------------
// HMMA bf16 GEMM:  C[M,N] = A3[M,K3] * B3[N,K3]^T
// mode 0: C fp32   mode 1: C = acc + add   mode 3: silu(acc)*add -> bf16 split
// 128x128 tile, BK=64, 3-stage cp.async, 256 thr, warp tile 64x32
// ---------------------------------------------------------------------------
#define GSTAGES      3
#define GTILE_BYTES  16384
#define GSTAGE_BYTES (2 * GTILE_BYTES)
#define GEMM_DSMEM   (GSTAGES * GSTAGE_BYTES)   // 96 KB

__global__ void __launch_bounds__(256, 2) gemm3_kernel(
    const __nv_bfloat16* __restrict__ A, const __nv_bfloat16* __restrict__ B,
    const float* __restrict__ add, float* __restrict__ C,
    __nv_bfloat16* __restrict__ out3,
    int M, int N, int K3, int mode)
{
    extern __shared__ __align__(128) char smem[];
    const uint32_t smem_base = smem_u32(smem);

    const int tid  = threadIdx.x;
    const int lane = tid & 31;
    const int warp = tid >> 5;
    const int wm = warp >> 2;
    const int wn = warp & 3;
    const int bx = blockIdx.x, by = blockIdx.y;
    const int nk = K3 >> 6;

    int lrow[4], lswz[4];
#pragma unroll
    for (int p = 0; p < 4; p++) {
        const int id = p * 256 + tid;
        const int row = id >> 3;
        const int c   = id & 7;
        lrow[p] = row;
        lswz[p] = row * 128 + ((c ^ (row & 7)) << 4);
    }
    const __nv_bfloat16* Abase = A + (size_t)(by * 128) * K3;
    const __nv_bfloat16* Bbase = B + (size_t)(bx * 128) * K3;

    float acc[4][4][4];
#pragma unroll
    for (int i = 0; i < 4; i++)
#pragma unroll
        for (int j = 0; j < 4; j++)
#pragma unroll
            for (int r = 0; r < 4; r++) acc[i][j][r] = 0.f;

    auto load_tile = [&](int ks, int buf) {
        const uint32_t sa = smem_base + buf * GSTAGE_BYTES;
        const uint32_t sb = sa + GTILE_BYTES;
        const int koff = ks * 64;
#pragma unroll
        for (int p = 0; p < 4; p++) {
            const int id = p * 256 + tid;
            const int c  = id & 7;
            CP_ASYNC16(sa + lswz[p], Abase + (size_t)lrow[p] * K3 + koff + c * 8);
            CP_ASYNC16(sb + lswz[p], Bbase + (size_t)lrow[p] * K3 + koff + c * 8);
        }
    };

    load_tile(0, 0); CP_COMMIT();
    load_tile(1, 1); CP_COMMIT();

    for (int ks = 0; ks < nk; ks++) {
        CP_WAIT1();
        __syncthreads();
        if (ks + 2 < nk) load_tile(ks + 2, (ks + 2) % GSTAGES);
        CP_COMMIT();

        const int buf = ks % GSTAGES;
        const uint32_t sa = smem_base + buf * GSTAGE_BYTES;
        const uint32_t sb = sa + GTILE_BYTES;

#pragma unroll
        for (int kk = 0; kk < 4; kk++) {
            uint32_t ra[4][4];
#pragma unroll
            for (int mt = 0; mt < 4; mt++) {
                const int row = wm * 64 + mt * 16 + (lane & 15);
                const int ch  = kk * 2 + (lane >> 4);
                LDSM4(ra[mt], sa + row * 128 + ((ch ^ (row & 7)) << 4));
            }
            uint32_t rb[2][4];
#pragma unroll
            for (int pr = 0; pr < 2; pr++) {
                const int n  = wn * 32 + pr * 16 + (lane & 7) + ((lane >> 4) << 3);
                const int ch = kk * 2 + ((lane >> 3) & 1);
                LDSM4(rb[pr], sb + n * 128 + ((ch ^ (n & 7)) << 4));
            }
#pragma unroll
            for (int mt = 0; mt < 4; mt++)
#pragma unroll
                for (int nt = 0; nt < 4; nt++)
                    MMA16816(acc[mt][nt], ra[mt],
                             rb[nt >> 1][(nt & 1) * 2], rb[nt >> 1][(nt & 1) * 2 + 1]);
        }
    }

    // epilogue
    const int r0 = lane >> 2;
    const int c0 = (lane & 3) * 2;
#pragma unroll
    for (int mt = 0; mt < 4; mt++) {
#pragma unroll
        for (int half = 0; half < 2; half++) {
            const int row = by * 128 + wm * 64 + mt * 16 + r0 + half * 8;
            const int colb = bx * 128 + wn * 32;
            if (mode == 3) {
                const float* Ur = add + (size_t)row * N + colb;
                __nv_bfloat16* Or = out3 + (size_t)row * (3 * N) + colb;
#pragma unroll
                for (int nt = 0; nt < 4; nt++) {
                    const float2 uv = *(const float2*)(Ur + nt * 8 + c0);
                    float g0 = acc[mt][nt][half * 2];
                    float g1 = acc[mt][nt][half * 2 + 1];
                    g0 = g0 / (1.f + expf(-g0)) * uv.x;
                    g1 = g1 / (1.f + expf(-g1)) * uv.y;
                    const int c = nt * 8 + c0;
                    __nv_bfloat16 h0 = __float2bfloat16(g0);
                    __nv_bfloat16 h1 = __float2bfloat16(g1);
                    __nv_bfloat16 l0 = __float2bfloat16(g0 - __bfloat162float(h0));
                    __nv_bfloat16 l1 = __float2bfloat16(g1 - __bfloat162float(h1));
                    Or[c] = h0; Or[c + 1] = h1;
                    Or[N + c] = l0; Or[N + c + 1] = l1;
                    Or[2 * N + c] = h0; Or[2 * N + c + 1] = h1;
                }
            } else {
                float* Cr = C + (size_t)row * N + colb;
                const float* Ar = (mode == 1) ? add + (size_t)row * N + colb : nullptr;
#pragma unroll
                for (int nt = 0; nt < 4; nt++) {
                    float2 o;
                    o.x = acc[mt][nt][half * 2];
                    o.y = acc[mt][nt][half * 2 + 1];
                    if (Ar) {
                        const float2 av = *(const float2*)(Ar + nt * 8 + c0);
                        o.x += av.x; o.y += av.y;
                    }
                    *(float2*)(Cr + nt * 8 + c0) = o;
                }
            }
        }
    }
}

// ---------------------------------------------------------------------------
// Flash attention, bf16 HMMA w/ 3-split, fp32 online softmax.
// Block: 128 q-rows x one head. 256 thr = 8 warps (16 q-rows each).
// Writes ctx directly as bf16 3-split [hi|lo|hi] into ctx3 (stride 3*HID).
// ---------------------------------------------------------------------------
#define QS_STRIDE 200     // 192 data + 8 pad (bf16 elems)
#define VT_STRIDE 136     // 128 + 8 pad
#define FA_SMEM   (2*(128*QS_STRIDE*2) + 2*(64*VT_STRIDE*2))   // 137216 B

__global__ void __launch_bounds__(256, 1) flash_attn_kernel(
    const float* __restrict__ q, const float* __restrict__ k,
    const float* __restrict__ v, const float* __restrict__ mask,
    __nv_bfloat16* __restrict__ ctx3)
{
    extern __shared__ __align__(128) char smem[];
    __nv_bfloat16* Qs  = (__nv_bfloat16*)smem;
    __nv_bfloat16* Ks  = Qs + 128 * QS_STRIDE;
    __nv_bfloat16* Vth = Ks + 128 * QS_STRIDE;
    __nv_bfloat16* Vtl = Vth + 64 * VT_STRIDE;
    const uint32_t QsB  = smem_u32(Qs);
    const uint32_t KsB  = smem_u32(Ks);
    const uint32_t VthB = smem_u32(Vth);
    const uint32_t VtlB = smem_u32(Vtl);

    const int tid  = threadIdx.x;
    const int lane = tid & 31;
    const int w    = tid >> 5;
    const int bh = blockIdx.y;
    const int b = bh >> 5, h = bh & 31;
    const int q0 = blockIdx.x * 128;

    // ---- load Q tile once, 3-split [Qh|Ql|Qh] ----
#pragma unroll
    for (int p = 0; p < 8; p++) {
        const int id = p * 256 + tid;          // 0..2047
        const int row = id >> 4;
        const int c4  = (id & 15) * 4;
        const float4 vv = *(const float4*)(q + (size_t)(b * SS + q0 + row) * HID + h * HD + c4);
        const float xs[4] = {vv.x, vv.y, vv.z, vv.w};
#pragma unroll
        for (int j = 0; j < 4; j++) {
            __nv_bfloat16 hi = __float2bfloat16(xs[j]);
            __nv_bfloat16 lo = __float2bfloat16(xs[j] - __bfloat162float(hi));
            Qs[row * QS_STRIDE + c4 + j]       = hi;
            Qs[row * QS_STRIDE + 64 + c4 + j]  = lo;
            Qs[row * QS_STRIDE + 128 + c4 + j] = hi;
        }
    }

    float sc[64];          // 16 n-tiles x 4
    float o[8][4];
#pragma unroll
    for (int j = 0; j < 8; j++)
#pragma unroll
        for (int r = 0; r < 4; r++) o[j][r] = 0.f;
    float mrow[2] = {-INFINITY, -INFINITY};
    float lrow[2] = {0.f, 0.f};

    const int rA = lane >> 2;              // row within warp tile
    const int cA = (lane & 3) * 2;

    for (int kt = 0; kt < SS / 128; kt++) {
        __syncthreads();
        // ---- load K tile, split [Kh|Kh|Kl] ----
#pragma unroll
        for (int p = 0; p < 8; p++) {
            const int id = p * 256 + tid;
            const int row = id >> 4;
            const int c4  = (id & 15) * 4;
            const float4 vv = *(const float4*)(k + (size_t)(b * SS + kt * 128 + row) * HID + h * HD + c4);
            const float xs[4] = {vv.x, vv.y, vv.z, vv.w};
#pragma unroll
            for (int j = 0; j < 4; j++) {
                __nv_bfloat16 hi = __float2bfloat16(xs[j]);
                __nv_bfloat16 lo = __float2bfloat16(xs[j] - __bfloat162float(hi));
                Ks[row * QS_STRIDE + c4 + j]       = hi;
                Ks[row * QS_STRIDE + 64 + c4 + j]  = hi;
                Ks[row * QS_STRIDE + 128 + c4 + j] = lo;
            }
        }
        // ---- load V tile transposed, hi/lo ----
#pragma unroll
        for (int p = 0; p < 8; p++) {
            const int id = p * 256 + tid;
            const int krow = id >> 4;
            const int c4   = (id & 15) * 4;
            const float4 vv = *(const float4*)(v + (size_t)(b * SS + kt * 128 + krow) * HID + h * HD + c4);
            const float xs[4] = {vv.x, vv.y, vv.z, vv.w};
#pragma unroll
            for (int j = 0; j < 4; j++) {
                __nv_bfloat16 hi = __float2bfloat16(xs[j]);
                __nv_bfloat16 lo = __float2bfloat16(xs[j] - __bfloat162float(hi));
                Vth[(c4 + j) * VT_STRIDE + krow] = hi;
                Vtl[(c4 + j) * VT_STRIDE + krow] = lo;
            }
        }
        __syncthreads();

        // ---- scores: S = Q3 . K3^T  (K3=192) ----
#pragma unroll
        for (int i = 0; i < 64; i++) sc[i] = 0.f;
#pragma unroll
        for (int s = 0; s < 12; s++) {
            uint32_t ra[4];
            const int arow = 16 * w + (lane & 15);
            LDSM4(ra, QsB + (arow * QS_STRIDE + s * 16 + ((lane >> 4) << 3)) * 2);
#pragma unroll
            for (int t2 = 0; t2 < 8; t2++) {
                uint32_t rb[4];
                const int n  = t2 * 16 + (lane & 7) + ((lane >> 4) << 3);
                const int cb = s * 16 + (((lane >> 3) & 1) << 3);
                LDSM4(rb, KsB + (n * QS_STRIDE + cb) * 2);
                MMA16816((sc + (2 * t2) * 4),     ra, rb[0], rb[1]);
                MMA16816((sc + (2 * t2 + 1) * 4), ra, rb[2], rb[3]);
            }
        }

        // ---- scale + mask, online softmax ----
        const int qrA = q0 + 16 * w + rA;
        const int qrB = qrA + 8;
        float tm[2] = {-INFINITY, -INFINITY};
#pragma unroll
        for (int t = 0; t < 16; t++) {
            const int kc = kt * 128 + t * 8 + cA;
            const float2 mA = *(const float2*)(mask + ((size_t)b * SS + qrA) * SS + kc);
            const float2 mB = *(const float2*)(mask + ((size_t)b * SS + qrB) * SS + kc);
            sc[t * 4 + 0] = sc[t * 4 + 0] * 0.125f + mA.x;
            sc[t * 4 + 1] = sc[t * 4 + 1] * 0.125f + mA.y;
            sc[t * 4 + 2] = sc[t * 4 + 2] * 0.125f + mB.x;
            sc[t * 4 + 3] = sc[t * 4 + 3] * 0.125f + mB.y;
            tm[0] = fmaxf(tm[0], fmaxf(sc[t * 4 + 0], sc[t * 4 + 1]));
            tm[1] = fmaxf(tm[1], fmaxf(sc[t * 4 + 2], sc[t * 4 + 3]));
        }
#pragma unroll
        for (int off = 1; off <= 2; off <<= 1) {
            tm[0] = fmaxf(tm[0], __shfl_xor_sync(0xffffffffu, tm[0], off));
            tm[1] = fmaxf(tm[1], __shfl_xor_sync(0xffffffffu, tm[1], off));
        }
        const float mn0 = fmaxf(mrow[0], tm[0]);
        const float mn1 = fmaxf(mrow[1], tm[1]);
        const float sc0 = __expf(mrow[0] - mn0);
        const float sc1 = __expf(mrow[1] - mn1);
        float ts[2] = {0.f, 0.f};
#pragma unroll
        for (int t = 0; t < 16; t++) {
            sc[t * 4 + 0] = __expf(sc[t * 4 + 0] - mn0);
            sc[t * 4 + 1] = __expf(sc[t * 4 + 1] - mn0);
            sc[t * 4 + 2] = __expf(sc[t * 4 + 2] - mn1);
            sc[t * 4 + 3] = __expf(sc[t * 4 + 3] - mn1);
            ts[0] += sc[t * 4 + 0] + sc[t * 4 + 1];
            ts[1] += sc[t * 4 + 2] + sc[t * 4 + 3];
        }
#pragma unroll
        for (int off = 1; off <= 2; off <<= 1) {
            ts[0] += __shfl_xor_sync(0xffffffffu, ts[0], off);
            ts[1] += __shfl_xor_sync(0xffffffffu, ts[1], off);
        }
        lrow[0] = lrow[0] * sc0 + ts[0];
        lrow[1] = lrow[1] * sc1 + ts[1];
        mrow[0] = mn0; mrow[1] = mn1;
#pragma unroll
        for (int j = 0; j < 8; j++) {
            o[j][0] *= sc0; o[j][1] *= sc0;
            o[j][2] *= sc1; o[j][3] *= sc1;
        }

        // ---- O += P3 . V3 (3-term split) ----
#pragma unroll
        for (int s2 = 0; s2 < 8; s2++) {
            const float p00 = sc[(2 * s2) * 4 + 0], p01 = sc[(2 * s2) * 4 + 1];
            const float p10 = sc[(2 * s2) * 4 + 2], p11 = sc[(2 * s2) * 4 + 3];
            const float r00 = sc[(2 * s2 + 1) * 4 + 0], r01 = sc[(2 * s2 + 1) * 4 + 1];
            const float r10 = sc[(2 * s2 + 1) * 4 + 2], r11 = sc[(2 * s2 + 1) * 4 + 3];
            uint32_t ph[4], pl[4];
            ph[0] = pack_bf2(p00, p01); ph[1] = pack_bf2(p10, p11);
            ph[2] = pack_bf2(r00, r01); ph[3] = pack_bf2(r10, r11);
            pl[0] = pack_bf2(p00 - __bfloat162float(__float2bfloat16(p00)),
                             p01 - __bfloat162float(__float2bfloat16(p01)));
            pl[1] = pack_bf2(p10 - __bfloat162float(__float2bfloat16(p10)),
                             p11 - __bfloat162float(__float2bfloat16(p11)));
            pl[2] = pack_bf2(r00 - __bfloat162float(__float2bfloat16(r00)),
                             r01 - __bfloat162float(__float2bfloat16(r01)));
            pl[3] = pack_bf2(r10 - __bfloat162float(__float2bfloat16(r10)),
                             r11 - __bfloat162float(__float2bfloat16(r11)));
#pragma unroll
            for (int dt = 0; dt < 4; dt++) {
                uint32_t bh_[4], bl_[4];
                const int n  = dt * 16 + (lane & 7) + ((lane >> 4) << 3);
                const int cb = s2 * 16 + (((lane >> 3) & 1) << 3);
                LDSM4(bh_, VthB + (n * VT_STRIDE + cb) * 2);
                LDSM4(bl_, VtlB + (n * VT_STRIDE + cb) * 2);
                MMA16816(o[2 * dt],     ph, bh_[0], bh_[1]);
                MMA16816(o[2 * dt + 1], ph, bh_[2], bh_[3]);
                MMA16816(o[2 * dt],     pl, bh_[0], bh_[1]);
                MMA16816(o[2 * dt + 1], pl, bh_[2], bh_[3]);
                MMA16816(o[2 * dt],     ph, bl_[0], bl_[1]);
                MMA16816(o[2 * dt + 1], ph, bl_[2], bl_[3]);
            }
        }
    }

    // ---- epilogue: normalize, write bf16 3-split ctx ----
    const float inv0 = 1.f / lrow[0];
    const float inv1 = 1.f / lrow[1];
    const size_t tokA = (size_t)(b * SS + q0 + 16 * w + rA);
    const size_t tokB = tokA + 8;
#pragma unroll
    for (int j = 0; j < 8; j++) {
        const int cg = h * HD + j * 8 + cA;
#pragma unroll
        for (int e = 0; e < 2; e++) {
            {
                const float val = o[j][e] * inv0;
                __nv_bfloat16 hi = __float2bfloat16(val);
                __nv_bfloat16 lo = __float2bfloat16(val - __bfloat162float(hi));
                __nv_bfloat16* p = ctx3 + tokA * (3 * HID) + cg + e;
                p[0] = hi; p[HID] = lo; p[2 * HID] = hi;
            }
            {
                const float val = o[j][2 + e] * inv1;
                __nv_bfloat16 hi = __float2bfloat16(val);
                __nv_bfloat16 lo = __float2bfloat16(val - __bfloat162float(hi));
                __nv_bfloat16* p = ctx3 + tokB * (3 * HID) + cg + e;
                p[0] = hi; p[HID] = lo; p[2 * HID] = hi;
            }
        }
    }
}

// ---------------------------------------------------------------------------
// fp32 -> bf16 3-split. brole=0: [hi|lo|hi]  brole=1: [hi|hi|lo]
// ---------------------------------------------------------------------------
__global__ void __launch_bounds__(256) split3_kernel(
    const float* __restrict__ X, __nv_bfloat16* __restrict__ Y, int C, int brole)
{
    const size_t e = ((size_t)blockIdx.x * 256 + threadIdx.x) * 4;
    const size_t r = e / (size_t)C;
    const int   c = (int)(e - r * (size_t)C);
    const float4 v = *(const float4*)(X + e);
    float xs[4] = {v.x, v.y, v.z, v.w};
    uint32_t hpx = 0, hpy = 0, lpx = 0, lpy = 0;
#pragma unroll
    for (int j = 0; j < 4; j++) {
        __nv_bfloat16 h = __float2bfloat16(xs[j]);
        __nv_bfloat16 l = __float2bfloat16(xs[j] - __bfloat162float(h));
        uint32_t hu = (uint32_t)__bfloat16_as_ushort(h);
        uint32_t lu = (uint32_t)__bfloat16_as_ushort(l);
        if (j < 2) { hpx |= hu << (16 * j); lpx |= lu << (16 * j); }
        else       { hpy |= hu << (16 * (j - 2)); lpy |= lu << (16 * (j - 2)); }
    }
    uint2 hp = make_uint2(hpx, hpy), lp = make_uint2(lpx, lpy);
    __nv_bfloat16* yb = Y + r * (size_t)(3 * C) + c;
    *(uint2*)(yb)         = hp;
    *(uint2*)(yb + C)     = brole ? hp : lp;
    *(uint2*)(yb + 2 * C) = brole ? lp : hp;
}

// ---------------------------------------------------------------------------
// LayerNorm
// ---------------------------------------------------------------------------
__global__ void __launch_bounds__(256) layernorm_kernel(
    const float* __restrict__ x, const float* __restrict__ w,
    const float* __restrict__ b, float* __restrict__ out)
{
    const int t   = blockIdx.x;
    const int tid = threadIdx.x;
    const float* xr = x + (size_t)t * HID;

    float v[8];
    float s = 0.f, s2 = 0.f;
#pragma unroll
    for (int i = 0; i < 8; i++) {
        v[i] = xr[tid + i * 256];
        s  += v[i];
        s2 += v[i] * v[i];
    }
#pragma unroll
    for (int o = 16; o; o >>= 1) {
        s  += __shfl_xor_sync(0xffffffffu, s,  o);
        s2 += __shfl_xor_sync(0xffffffffu, s2, o);
    }
    __shared__ float ss[8], ss2[8];
    if ((tid & 31) == 0) { ss[tid >> 5] = s; ss2[tid >> 5] = s2; }
    __syncthreads();
    if (tid < 32) {
        s  = (tid < 8) ? ss [tid] : 0.f;
        s2 = (tid < 8) ? ss2[tid] : 0.f;
#pragma unroll
        for (int o = 4; o; o >>= 1) {
            s  += __shfl_xor_sync(0xffffffffu, s,  o);
            s2 += __shfl_xor_sync(0xffffffffu, s2, o);
        }
        if (tid == 0) { ss[0] = s; ss2[0] = s2; }
    }
    __syncthreads();
    const float mean = ss[0] * (1.f / HID);
    const float var  = ss2[0] * (1.f / HID) - mean * mean;
    const float rstd = rsqrtf(var + LN_EPS);
    float* orow = out + (size_t)t * HID;
#pragma unroll
    for (int i = 0; i < 8; i++) {
        const int idx = tid + i * 256;
        orow[idx] = (v[i] - mean) * rstd * w[idx] + b[idx];
    }
}

// ---------------------------------------------------------------------------
// Partial RoPE
// ---------------------------------------------------------------------------
__global__ void __launch_bounds__(256) rope_kernel(
    float* __restrict__ q, float* __restrict__ k, const int* __restrict__ pos_ids)
{
    const int idx = blockIdx.x * blockDim.x + threadIdx.x;
    if (idx >= TT * NH * 8) return;
    const int i = idx & 7;
    const int h = (idx >> 3) & 31;
    const int t = idx >> 8;
    const int b = t / SS, s = t % SS;
    const int pos = pos_ids[b * SS + s];

    const float freq = powf(10000.0f, -(2.0f * (float)i) / (float)ROT);
    const float ang  = (float)pos * freq;
    float c, si;
    sincosf(ang, &si, &c);

    const size_t base = (size_t)t * HID + h * HD;
    float q0 = q[base + i], q1 = q[base + i + 8];
    q[base + i]     = q0 * c - q1 * si;
    q[base + i + 8] = q1 * c + q0 * si;
    float k0 = k[base + i], k1 = k[base + i + 8];
    k[base + i]     = k0 * c - k1 * si;
    k[base + i + 8] = k1 * c + k0 * si;
}

// ---------------------------------------------------------------------------
// Launch
// ---------------------------------------------------------------------------
extern "C" void kernel_launch(void* const* d_in, const int* in_sizes, int n_in,
                              void* d_out, int out_size)
{
    const float* hidden = (const float*)d_in[0];
    const float* memory = (const float*)d_in[1];
    const float* mask   = (const float*)d_in[2];
    const int*   pos    = (const int*)  d_in[3];
    const float* Wq     = (const float*)d_in[4];
    const float* Wk     = (const float*)d_in[5];
    const float* Wv     = (const float*)d_in[6];
    const float* Wo     = (const float*)d_in[7];
    const float* ln1w   = (const float*)d_in[8];
    const float* ln1b   = (const float*)d_in[9];
    const float* ln2w   = (const float*)d_in[10];
    const float* ln2b   = (const float*)d_in[11];
    const float* gw     = (const float*)d_in[12];
    const float* uw     = (const float*)d_in[13];
    const float* dw     = (const float*)d_in[14];
    float* out = (float*)d_out;

    float *xln, *q, *k, *v, *h, *yln, *up;
    __nv_bfloat16 *a3, *b3, *c3;
    cudaGetSymbolAddress((void**)&xln,  g_xln);
    cudaGetSymbolAddress((void**)&q,    g_q);
    cudaGetSymbolAddress((void**)&k,    g_k);
    cudaGetSymbolAddress((void**)&v,    g_v);
    cudaGetSymbolAddress((void**)&h,    g_h);
    cudaGetSymbolAddress((void**)&yln,  g_yln);
    cudaGetSymbolAddress((void**)&up,   g_up);
    cudaGetSymbolAddress((void**)&a3,   g_a3);
    cudaGetSymbolAddress((void**)&b3,   g_b3);
    cudaGetSymbolAddress((void**)&c3,   g_c3);

    cudaFuncSetAttribute(gemm3_kernel,
                         cudaFuncAttributeMaxDynamicSharedMemorySize, GEMM_DSMEM);
    cudaFuncSetAttribute(flash_attn_kernel,
                         cudaFuncAttributeMaxDynamicSharedMemorySize, FA_SMEM);

    auto gemm = [&](const __nv_bfloat16* A, const __nv_bfloat16* B,
                    const float* add, float* C, __nv_bfloat16* O3,
                    int M, int N, int K3, int mode) {
        gemm3_kernel<<<dim3(N / 128, M / 128), 256, GEMM_DSMEM>>>(
            A, B, add, C, O3, M, N, K3, mode);
    };
    auto split = [&](const float* X, __nv_bfloat16* Y, int R, int C, int brole) {
        split3_kernel<<<(unsigned)((size_t)R * C / 1024), 256>>>(X, Y, C, brole);
    };

    // 1) LN1
    layernorm_kernel<<<TT, 256>>>(hidden, ln1w, ln1b, xln);

    // 2) Q projection
    split(xln, a3, TT, HID, 0);
    split(Wq,  b3, HID, HID, 1);
    gemm(a3, b3, nullptr, q, nullptr, TT, HID, 3 * HID, 0);

    // 3) K/V projections from memory
    split(memory, a3, TT, HID, 0);
    split(Wk, b3, HID, HID, 1);
    gemm(a3, b3, nullptr, k, nullptr, TT, HID, 3 * HID, 0);
    split(Wv, b3, HID, HID, 1);
    gemm(a3, b3, nullptr, v, nullptr, TT, HID, 3 * HID, 0);

    // 4) RoPE
    rope_kernel<<<(TT * NH * 8) / 256, 256>>>(q, k, pos);

    // 5) fused flash attention -> ctx split directly into a3
    flash_attn_kernel<<<dim3(SS / 128, BB * NH), 256, FA_SMEM>>>(q, k, v, mask, a3);

    // 6) O projection + residual
    split(Wo, b3, HID, HID, 1);
    gemm(a3, b3, hidden, h, nullptr, TT, HID, 3 * HID, 1);

    // 7) LN2
    layernorm_kernel<<<TT, 256>>>(h, ln2w, ln2b, yln);

    // 8) SwiGLU MLP + residual
    split(yln, a3, TT, HID, 0);
    split(uw, b3, DFF, HID, 1);
    gemm(a3, b3, nullptr, up, nullptr, TT, DFF, 3 * HID, 0);
    split(gw, b3, DFF, HID, 1);
    gemm(a3, b3, up, nullptr, c3, TT, DFF, 3 * HID, 3);   // silu*up -> split
    split(dw, b3, HID, DFF, 1);
    gemm(c3, b3, h, out, nullptr, TT, HID, 3 * DFF, 1);
}